// round 2
// baseline (speedup 1.0000x reference)
#include <cuda_runtime.h>
#include <stdint.h>

// ---------------- problem constants ----------------
#define MAXM      300000
#define NCLS      80
#define TOPK      1000
#define CONF      0.001f
#define NMSTH     0.5f
#define CLSOFF    4096.0f
#define CAND_CAP  4096
#define NBINS     4096
#define SUPSTRIDE 1025     // 32 words x 1025 stride -> conflict-free rows & cols

// ---------------- device scratch (zero-initialized at load) ----------------
__device__ uint32_t g_scorebits[MAXM];
__device__ int32_t  g_label[MAXM];
__device__ uint32_t g_hist[NBINS];     // kept zero between replays by k_select
__device__ uint32_t g_prefix;
__device__ uint32_t g_need;
__device__ uint32_t g_cand_cnt;
__device__ unsigned long long g_cand[CAND_CAP];
__device__ float    g_tk_score[TOPK];
__device__ int32_t  g_tk_label[TOPK];
__device__ float4   g_tk_box[TOPK];

__device__ __forceinline__ float sigf(float x) {
    return 1.0f / (1.0f + expf(-x));
}

// ---------------- pass 1: max-logit argmax + exact fused score + 12-bit hist ----------------
__global__ void k_score(const float* __restrict__ obj,
                        const float* __restrict__ cls, int M) {
    __shared__ uint32_t sh[NBINS];
    for (int i = threadIdx.x; i < NBINS; i += blockDim.x) sh[i] = 0;
    __syncthreads();

    int m = blockIdx.x * blockDim.x + threadIdx.x;
    if (m < M) {
        const float4* c4 = (const float4*)(cls + (size_t)m * NCLS);
        float best = -1e30f;
        int lab = 0;
#pragma unroll
        for (int q = 0; q < NCLS / 4; q++) {
            float4 v = c4[q];
            if (v.x > best) { best = v.x; lab = q * 4 + 0; }
            if (v.y > best) { best = v.y; lab = q * 4 + 1; }
            if (v.z > best) { best = v.z; lab = q * 4 + 2; }
            if (v.w > best) { best = v.w; lab = q * 4 + 3; }
        }
        // monotone: max_c sqrt(sig(o)*sig(c)) == sqrt(sig(o)*sig(max_c))
        float f = sqrtf(sigf(obj[m]) * sigf(best));
        uint32_t bits = __float_as_uint(f);   // positive float: uint order == float order
        g_scorebits[m] = bits;
        g_label[m] = lab;
        atomicAdd(&sh[bits >> 20], 1u);
    }
    __syncthreads();
    for (int i = threadIdx.x; i < NBINS; i += blockDim.x) {
        uint32_t v = sh[i];
        if (v) atomicAdd(&g_hist[i], v);
    }
}

// ---------------- pick bin holding the k-th largest, zero hist, reset state ----------------
__global__ void k_select(int shift, int first) {
    __shared__ uint32_t ssum[1024];
    int t = threadIdx.x;
    uint32_t h0 = g_hist[t * 4 + 0];
    uint32_t h1 = g_hist[t * 4 + 1];
    uint32_t h2 = g_hist[t * 4 + 2];
    uint32_t h3 = g_hist[t * 4 + 3];
    ssum[t] = h0 + h1 + h2 + h3;
    uint32_t need = first ? (uint32_t)TOPK : g_need;
    uint32_t oldpre = first ? 0u : g_prefix;
    __syncthreads();
    for (int off = 1; off < 1024; off <<= 1) {
        uint32_t v = (t + off < 1024) ? ssum[t + off] : 0u;
        __syncthreads();
        ssum[t] += v;
        __syncthreads();
    }
    uint32_t cum = (t < 1023) ? ssum[t + 1] : 0u;
    uint32_t hh[4] = {h0, h1, h2, h3};
#pragma unroll
    for (int c = 3; c >= 0; c--) {
        uint32_t bc = hh[c];
        if (bc > 0 && cum < need && cum + bc >= need) {
            uint32_t bin = (uint32_t)(t * 4 + c);
            g_prefix = oldpre | (bin << shift);
            g_need   = need - cum;
        }
        cum += bc;
    }
    g_hist[t * 4 + 0] = 0;
    g_hist[t * 4 + 1] = 0;
    g_hist[t * 4 + 2] = 0;
    g_hist[t * 4 + 3] = 0;
    if (t == 0) g_cand_cnt = 0;
}

// ---------------- refinement hist: 12 more bits among prefix-matching elements ----------------
__global__ void k_hist2(int M) {
    __shared__ uint32_t sh[NBINS];
    for (int i = threadIdx.x; i < NBINS; i += blockDim.x) sh[i] = 0;
    __syncthreads();
    uint32_t pre = g_prefix;  // (bin << 20)
    const uint4* sb4 = (const uint4*)g_scorebits;
    int n4 = M >> 2;
    for (int i = blockIdx.x * blockDim.x + threadIdx.x; i < n4;
         i += gridDim.x * blockDim.x) {
        uint4 v = sb4[i];
        if ((v.x & 0xFFF00000u) == pre) atomicAdd(&sh[(v.x >> 8) & 0xFFFu], 1u);
        if ((v.y & 0xFFF00000u) == pre) atomicAdd(&sh[(v.y >> 8) & 0xFFFu], 1u);
        if ((v.z & 0xFFF00000u) == pre) atomicAdd(&sh[(v.z >> 8) & 0xFFFu], 1u);
        if ((v.w & 0xFFF00000u) == pre) atomicAdd(&sh[(v.w >> 8) & 0xFFFu], 1u);
    }
    if (blockIdx.x == 0 && (int)threadIdx.x < (M & 3)) {
        uint32_t b = g_scorebits[(n4 << 2) + threadIdx.x];
        if ((b & 0xFFF00000u) == pre) atomicAdd(&sh[(b >> 8) & 0xFFFu], 1u);
    }
    __syncthreads();
    for (int i = threadIdx.x; i < NBINS; i += blockDim.x) {
        uint32_t v = sh[i];
        if (v) atomicAdd(&g_hist[i], v);
    }
}

// ---------------- gather all candidates with bits >= 24-bit threshold ----------------
__global__ void k_gather(int M) {
    uint32_t T = g_prefix;
    const uint4* sb4 = (const uint4*)g_scorebits;
    int n4 = M >> 2;
    for (int i = blockIdx.x * blockDim.x + threadIdx.x; i < n4;
         i += gridDim.x * blockDim.x) {
        uint4 v = sb4[i];
        uint32_t m0 = (uint32_t)(i << 2);
        uint32_t bb[4] = {v.x, v.y, v.z, v.w};
#pragma unroll
        for (int c = 0; c < 4; c++) {
            if (bb[c] >= T) {
                uint32_t p = atomicAdd(&g_cand_cnt, 1u);
                if (p < CAND_CAP)
                    g_cand[p] = ((unsigned long long)bb[c] << 32) |
                                (unsigned long long)(0xFFFFFFFFu - (m0 + c));
            }
        }
    }
    if (blockIdx.x == 0 && (int)threadIdx.x < (M & 3)) {
        uint32_t m = (uint32_t)((n4 << 2) + threadIdx.x);
        uint32_t b = g_scorebits[m];
        if (b >= T) {
            uint32_t p = atomicAdd(&g_cand_cnt, 1u);
            if (p < CAND_CAP)
                g_cand[p] = ((unsigned long long)b << 32) |
                            (unsigned long long)(0xFFFFFFFFu - m);
        }
    }
}

// ---------------- exact rank by counting (n ~ 1010): replaces bitonic sort ----------------
__global__ void k_rank(const float4* __restrict__ boxp) {
    __shared__ unsigned long long keys[CAND_CAP];
    int t = threadIdx.x;
    uint32_t n = g_cand_cnt;
    if (n > CAND_CAP) n = CAND_CAP;
    for (uint32_t i = t; i < n; i += 1024) keys[i] = g_cand[i];
    __syncthreads();
    for (uint32_t c = t; c < n; c += 1024) {
        unsigned long long k = keys[c];
        int r = 0;
        uint32_t j = 0;
        for (; j + 4 <= n; j += 4) {
            r += (keys[j + 0] > k);
            r += (keys[j + 1] > k);
            r += (keys[j + 2] > k);
            r += (keys[j + 3] > k);
        }
        for (; j < n; j++) r += (keys[j] > k);
        if (r < TOPK) {
            uint32_t idx = 0xFFFFFFFFu - (uint32_t)(k & 0xFFFFFFFFull);
            g_tk_score[r] = __uint_as_float((uint32_t)(k >> 32));
            g_tk_label[r] = g_label[idx];
            g_tk_box[r] = boxp[idx];
        }
    }
}

// ---------------- fused suppression matrix + sparse greedy sweep + output ----------------
__global__ void k_supnms(float* __restrict__ out, int out_size) {
    extern __shared__ char smem[];
    float* sx1   = (float*)smem;
    float* sy1   = sx1 + TOPK;
    float* sx2   = sy1 + TOPK;
    float* sy2   = sx2 + TOPK;
    float* sarea = sy2 + TOPK;
    float* sscr  = sarea + TOPK;
    int*   slab  = (int*)(sscr + TOPK);
    uint32_t* sup = (uint32_t*)(slab + TOPK);   // 32 * SUPSTRIDE words
    __shared__ uint32_t rowNZ[32];
    __shared__ uint32_t keep[32];

    int t = threadIdx.x;
    if (t < TOPK) {
        int lb = g_tk_label[t];
        float off = (float)lb * CLSOFF;
        float4 b = g_tk_box[t];
        float x1 = b.x + off, y1 = b.y + off;
        float x2 = b.z + off, y2 = b.w + off;
        sx1[t] = x1; sy1[t] = y1; sx2[t] = x2; sy2[t] = y2;
        sarea[t] = fmaxf(x2 - x1, 0.0f) * fmaxf(y2 - y1, 0.0f);
        slab[t] = lb;
        sscr[t] = g_tk_score[t];
    }
    if (t < 32) rowNZ[t] = 0;
    __syncthreads();

    if (t < 32) {
        uint32_t kw = 0;
        for (int b = 0; b < 32; b++) {
            int j = t * 32 + b;
            if (j < TOPK && sscr[j] > CONF) kw |= (1u << b);
        }
        keep[t] = kw;
    }

    int w = t >> 5;
    int lane = t & 31;
    int jbase = w * 32;
    for (int iter = 0; iter < 32; iter++) {
        int i = iter * 32 + lane;
        uint32_t bits = 0;
        if (i < TOPK && jbase < i) {
            int lb = slab[i];
            float ix1 = sx1[i], iy1 = sy1[i], ix2 = sx2[i], iy2 = sy2[i];
            float ia = sarea[i];
            int jend = jbase + 32; if (jend > i) jend = i;
            for (int j = jbase; j < jend; j++) {
                if (slab[j] == lb) {   // cross-class IoU is exactly 0 (offset geometry)
                    float xx1 = fmaxf(ix1, sx1[j]);
                    float yy1 = fmaxf(iy1, sy1[j]);
                    float xx2 = fminf(ix2, sx2[j]);
                    float yy2 = fminf(iy2, sy2[j]);
                    float inter = fmaxf(xx2 - xx1, 0.0f) * fmaxf(yy2 - yy1, 0.0f);
                    float iou = inter / (ia + sarea[j] - inter + 1e-9f);
                    if (iou > NMSTH) bits |= (1u << (j - jbase));
                }
            }
        }
        if (i < TOPK) {
            sup[w * SUPSTRIDE + i] = bits;
            if (bits) atomicOr(&rowNZ[i >> 5], 1u << (i & 31));
        }
    }
    __syncthreads();

    if (t < 32) {
        uint32_t kw = keep[lane];
        for (int w2 = 0; w2 < 32; w2++) {
            uint32_t rb = rowNZ[w2];
            while (rb) {
                int b = __ffs(rb) - 1;
                rb &= rb - 1;
                int i = w2 * 32 + b;
                int iw = i >> 5;
                uint32_t ib = (uint32_t)(i & 31);
                uint32_t ltm = (lane < iw) ? 0xFFFFFFFFu
                             : ((lane == iw) ? ((1u << ib) - 1u) : 0u);
                uint32_t v = sup[lane * SUPSTRIDE + i] & kw & ltm;
                if (__any_sync(0xFFFFFFFFu, v != 0u)) {
                    if (lane == iw) kw &= ~(1u << ib);
                }
            }
        }
        keep[lane] = kw;
    }
    __syncthreads();

    if (t < TOPK) {
        float kf = ((keep[t >> 5] >> (t & 31)) & 1u) ? 1.0f : 0.0f;
        float4 b = g_tk_box[t];            // raw (un-offset) box, matches reference
        out[t * 5 + 0] = sscr[t] * kf;
        out[t * 5 + 1] = b.x * kf;
        out[t * 5 + 2] = b.y * kf;
        out[t * 5 + 3] = b.z * kf;
        out[t * 5 + 4] = b.w * kf;
        if (out_size >= 6000) out[5000 + t] = (float)slab[t];
        if (out_size >= 7000) out[6000 + t] = kf;
    }
}

// ---------------- launch ----------------
extern "C" void kernel_launch(void* const* d_in, const int* in_sizes, int n_in,
                              void* d_out, int out_size) {
    const float* obj   = (const float*)d_in[0];
    const float* cls   = (const float*)d_in[1];
    const float4* boxp = (const float4*)d_in[2];
    float* out = (float*)d_out;
    int M = in_sizes[0];
    if (M > MAXM) M = MAXM;
    (void)n_in;

    const int SUP_SMEM =
        (int)(TOPK * 7 * sizeof(float)) + (int)(32 * SUPSTRIDE * sizeof(uint32_t));
    cudaFuncSetAttribute(k_supnms, cudaFuncAttributeMaxDynamicSharedMemorySize,
                         SUP_SMEM);

    int gs  = (M + 255) / 256;
    int gs4 = ((M >> 2) + 1023) / 1024;
    if (gs4 < 1) gs4 = 1;

    k_score<<<gs, 256>>>(obj, cls, M);
    k_select<<<1, 1024>>>(20, 1);
    k_hist2<<<gs4, 1024>>>(M);
    k_select<<<1, 1024>>>(8, 0);
    k_gather<<<gs4, 1024>>>(M);
    k_rank<<<1, 1024>>>(boxp);
    k_supnms<<<1, 1024, SUP_SMEM>>>(out, out_size);
}